// round 16
// baseline (speedup 1.0000x reference)
#include <cuda_runtime.h>
#include <cstdint>

#define BB 64
#define LL 1024
#define SS 8
#define DD 128
#define BL (BB*LL)          // 65536
#define NELEM (2*BL)        // 131072 element-sides
#define KEYSPACE 16384      // id*8 + (snap-1), id < 2000 -> key < 16000
#define NROWS 129           // 128 hot rows + 1 cold row

// ---- device scratch ----
__device__ float4   g_hot[128*32];            // hot joint table, 64KB
__device__ int      g_rowcnt[NROWS];          // per-row list lengths
__device__ uint32_t g_list[(size_t)NROWS*NELEM]; // per-row element-id lists
__device__ uint32_t g_coldpk[NELEM];          // packed counts for cold entries

// ============================================================
// Direct evaluation of one output row for (s, cx, cy).
// Warp-collective; lane holds float4 covering d' = 4*lane .. 4*lane+3.
// ============================================================
template <int UNROLL>
__device__ __forceinline__ float4 elem_eval(int s, int cx, int cy, int lane,
                              const float* __restrict__ aw1,
                              const float* __restrict__ ab1,
                              const float* __restrict__ aw2,
                              const float* __restrict__ ab2,
                              const float* __restrict__ ew1,
                              const float* __restrict__ eb1,
                              const float* __restrict__ ew2,
                              const float* __restrict__ eb2) {
    float fx = (float)cx, fy = (float)cy;
    float a0 = 0.f, a1 = 0.f;
#pragma unroll
    for (int m = 0; m < 4; ++m) {
        int d = lane + 32*m;
        float w = __ldg(&aw1[s*DD + d]);
        float b = __ldg(&ab1[d]);
        float h = fmaxf(fmaf(fx, w, b), 0.f) + fmaxf(fmaf(fy, w, b), 0.f);
        a0 = fmaf(h, __ldg(&aw2[2*d + 0]), a0);
        a1 = fmaf(h, __ldg(&aw2[2*d + 1]), a1);
    }
#pragma unroll
    for (int off = 16; off; off >>= 1) {
        a0 += __shfl_xor_sync(0xffffffffu, a0, off);
        a1 += __shfl_xor_sync(0xffffffffu, a1, off);
    }
    float y0 = fmaf(0.5f, a0, __ldg(&ab2[0]));
    float y1 = fmaf(0.5f, a1, __ldg(&ab2[1]));

    float4 e2 = __ldg(&((const float4*)eb2)[lane]);
    float4 acc;
    acc.x = 2.f*e2.x; acc.y = 2.f*e2.y; acc.z = 2.f*e2.z; acc.w = 2.f*e2.w;
    const float4* W2 = (const float4*)ew2;
#pragma unroll UNROLL
    for (int d = 0; d < DD; ++d) {
        float w = __ldg(&ew1[d]);
        float b = __ldg(&eb1[d]);
        float h = fmaxf(fmaf(y0, w, b), 0.f) + fmaxf(fmaf(y1, w, b), 0.f);
        float4 w2 = __ldg(&W2[d*32 + lane]);
        acc.x = fmaf(h, w2.x, acc.x);
        acc.y = fmaf(h, w2.y, acc.y);
        acc.z = fmaf(h, w2.z, acc.z);
        acc.w = fmaf(h, w2.w, acc.w);
    }
    return acc;
}

__device__ __noinline__ float4 elem_direct(int s, int cx, int cy, int lane,
                              const float* __restrict__ aw1,
                              const float* __restrict__ ab1,
                              const float* __restrict__ aw2,
                              const float* __restrict__ ab2,
                              const float* __restrict__ ew1,
                              const float* __restrict__ eb1,
                              const float* __restrict__ ew2,
                              const float* __restrict__ eb2) {
    return elem_eval<4>(s, cx, cy, lane, aw1, ab1, aw2, ab2, ew1, eb1, ew2, eb2);
}

// ============================================================
// Zero the per-row counters (must precede k_fused each replay).
// ============================================================
__global__ void k_zero() {
    if (threadIdx.x < NROWS) g_rowcnt[threadIdx.x] = 0;
}

// ============================================================
// Warp-aggregated rank: returns this thread's local slot within
// sm_cnt[row]; lanes with equal row share one smem atomic.
// ============================================================
__device__ __forceinline__ int rank_append(int row, int* sm_cnt, int lane) {
    unsigned m = __match_any_sync(0xffffffffu, row);
    int leader = __ffs(m) - 1;
    int prefix = __popc(m & ((1u << lane) - 1));
    int base = 0;
    if (lane == leader) base = atomicAdd(&sm_cnt[row], __popc(m));
    base = __shfl_sync(0xffffffffu, base, leader);
    return base + prefix;
}

// ============================================================
// Fused kernel. Block roles by blockIdx.x:
//   [0,64)  : per-batch histogram count -> per-row compacted lists
//   [64,96) : hot joint table, 4 rows per block (spread over 32 SMs)
// ============================================================
__global__ __launch_bounds__(1024, 1)
void k_fused(const int* __restrict__ sid, const int* __restrict__ did,
             const int* __restrict__ ssn, const int* __restrict__ dsn,
             const float* __restrict__ aw1, const float* __restrict__ ab1,
             const float* __restrict__ aw2, const float* __restrict__ ab2,
             const float* __restrict__ ew1, const float* __restrict__ eb1,
             const float* __restrict__ ew2, const float* __restrict__ eb2) {
    extern __shared__ uint32_t smraw[];
    int bid = blockIdx.x;
    int tid = threadIdx.x;
    int lane = tid & 31;

    if (bid < 64) {
        // ---------------- count + list-append section ----------------
        uint32_t* tabS = smraw;                 // KEYSPACE/2 words
        uint32_t* tabD = smraw + KEYSPACE/2;
        int* sm_cnt  = (int*)(smraw + KEYSPACE);        // NROWS
        int* sm_base = (int*)(smraw + KEYSPACE) + NROWS; // NROWS
        int b = bid;
        uint4* z = (uint4*)smraw;
#pragma unroll
        for (int i = 0; i < 4; ++i) z[tid + i*1024] = make_uint4(0,0,0,0);
        if (tid < NROWS) sm_cnt[tid] = 0;
        __syncthreads();

        int i = b*LL + tid;
        unsigned k1 = (unsigned)(sid[i]*8 + (ssn[i]-1));
        unsigned k2 = (unsigned)(did[i]*8 + (dsn[i]-1));
        k1 = min(k1, (unsigned)(KEYSPACE-1));
        k2 = min(k2, (unsigned)(KEYSPACE-1));
        atomicAdd(&tabS[k1>>1], 1u << ((k1&1)*16));
        atomicAdd(&tabD[k2>>1], 1u << ((k2&1)*16));
        __syncthreads();

        uint32_t cxS = (tabS[k1>>1] >> ((k1&1)*16)) & 0xFFFFu;
        uint32_t cyS = (tabD[k1>>1] >> ((k1&1)*16)) & 0xFFFFu;
        uint32_t cxD = (tabD[k2>>1] >> ((k2&1)*16)) & 0xFFFFu;
        uint32_t cyD = (tabS[k2>>1] >> ((k2&1)*16)) & 0xFFFFu;
        if (k1 < 8) { cxS = 0; cyS = 0; }     // id == 0 -> invalid
        if (k2 < 8) { cxD = 0; cyD = 0; }
        unsigned s1 = k1 & 7u, s2 = k2 & 7u;
        int rowA = ((cxS | cyS) < 4u) ? (int)((s1 << 4) | (cxS << 2) | cyS) : 128;
        int rowB = ((cxD | cyD) < 4u) ? (int)((s2 << 4) | (cxD << 2) | cyD) : 128;
        uint32_t pkA = cxS | (cyS << 11) | (s1 << 22);
        uint32_t pkB = cxD | (cyD << 11) | (s2 << 22);

        int rkA = rank_append(rowA, sm_cnt, lane);
        int rkB = rank_append(rowB, sm_cnt, lane);
        __syncthreads();

        if (tid < NROWS) sm_base[tid] = atomicAdd(&g_rowcnt[tid], sm_cnt[tid]);
        __syncthreads();

        uint32_t eA = (uint32_t)(b*LL + tid);
        uint32_t eB = (uint32_t)(BL + b*LL + tid);
        int slotA = sm_base[rowA] + rkA;
        int slotB = sm_base[rowB] + rkB;
        g_list[(size_t)rowA*NELEM + slotA] = eA;
        g_list[(size_t)rowB*NELEM + slotB] = eB;
        if (rowA == 128) g_coldpk[slotA] = pkA;
        if (rowB == 128) g_coldpk[slotB] = pkB;

    } else {
        // ---------------- hot-table section: 4 rows per block ----------------
        int wid = tid >> 5;
        if (wid < 4) {
            int ce = (bid - 64)*4 + wid;      // 0..127
            int s  = ce >> 4;
            int cx = (ce >> 2) & 3;
            int cy = ce & 3;
            g_hot[ce*32 + lane] = elem_eval<16>(s, cx, cy, lane,
                                                aw1, ab1, aw2, ab2,
                                                ew1, eb1, ew2, eb2);
        }
    }
}

// ============================================================
// Scatter kernel: 16 blocks per row (grid 129*16). Warp keeps its
// row in registers; per element: shfl id -> one STG.128. Cold row
// (128) decodes packed counts and computes directly.
// ============================================================
__global__ __launch_bounds__(256, 8)
void k_scatter(const float* __restrict__ aw1, const float* __restrict__ ab1,
               const float* __restrict__ aw2, const float* __restrict__ ab2,
               const float* __restrict__ ew1, const float* __restrict__ eb1,
               const float* __restrict__ ew2, const float* __restrict__ eb2,
               float4* __restrict__ out) {
    int lane = threadIdx.x & 31;
    int r = blockIdx.x >> 4;                 // 0..128
    int q = blockIdx.x & 15;
    int wip = q*8 + (threadIdx.x >> 5);      // warp-in-row 0..127
    int n = g_rowcnt[r];
    const uint32_t* lst = &g_list[(size_t)r*NELEM];

    if (r < 128) {
        float4 rv = g_hot[(r << 5) + lane];  // row lives in registers
        for (int j0 = wip*32; j0 < n; j0 += 128*32) {
            int cnt = min(32, n - j0);
            uint32_t e = (lane < cnt) ? lst[j0 + lane] : 0u;
            if (cnt == 32) {
#pragma unroll
                for (int i = 0; i < 32; ++i) {
                    uint32_t ei = __shfl_sync(0xffffffffu, e, i);
                    out[(size_t)ei*32 + lane] = rv;
                }
            } else {
                for (int i = 0; i < cnt; ++i) {
                    uint32_t ei = __shfl_sync(0xffffffffu, e, i);
                    out[(size_t)ei*32 + lane] = rv;
                }
            }
        }
    } else {
        // cold row: rare, compute directly
        for (int j0 = wip*32; j0 < n; j0 += 128*32) {
            int cnt = min(32, n - j0);
            uint32_t e  = (lane < cnt) ? lst[j0 + lane] : 0u;
            uint32_t pk = (lane < cnt) ? g_coldpk[j0 + lane] : 0u;
            for (int i = 0; i < cnt; ++i) {
                uint32_t ei  = __shfl_sync(0xffffffffu, e, i);
                uint32_t pki = __shfl_sync(0xffffffffu, pk, i);
                int cx = pki & 0x7FF;
                int cy = (pki >> 11) & 0x7FF;
                int s  = (pki >> 22) & 0xFF;
                float4 rr = elem_direct(s, cx, cy, lane,
                                        aw1, ab1, aw2, ab2, ew1, eb1, ew2, eb2);
                out[(size_t)ei*32 + lane] = rr;
            }
        }
    }
}

// ============================================================
extern "C" void kernel_launch(void* const* d_in, const int* in_sizes, int n_in,
                              void* d_out, int out_size) {
    const int*   sid = (const int*)d_in[0];
    const int*   did = (const int*)d_in[1];
    const int*   ssn = (const int*)d_in[2];
    const int*   dsn = (const int*)d_in[3];
    const float* aw1 = (const float*)d_in[5];
    const float* ab1 = (const float*)d_in[6];
    const float* aw2 = (const float*)d_in[7];
    const float* ab2 = (const float*)d_in[8];
    const float* ew1 = (const float*)d_in[9];
    const float* eb1 = (const float*)d_in[10];
    const float* ew2 = (const float*)d_in[11];
    const float* eb2 = (const float*)d_in[12];
    float4* out = (float4*)d_out;

    size_t fusedSmem = (size_t)KEYSPACE*sizeof(uint32_t) + 2*NROWS*sizeof(int) + 64;
    cudaFuncSetAttribute(k_fused, cudaFuncAttributeMaxDynamicSharedMemorySize, (int)fusedSmem);

    k_zero<<<1, 256>>>();
    k_fused<<<96, 1024, fusedSmem>>>(sid, did, ssn, dsn,
                                     aw1, ab1, aw2, ab2, ew1, eb1, ew2, eb2);
    k_scatter<<<NROWS*16, 256>>>(aw1, ab1, aw2, ab2, ew1, eb1, ew2, eb2, out);
}

// round 17
// speedup vs baseline: 1.7139x; 1.7139x over previous
#include <cuda_runtime.h>
#include <cstdint>

#define BB 64
#define LL 1024
#define SS 8
#define DD 128
#define BL (BB*LL)          // 65536
#define NELEM (2*BL)        // 131072 element-sides
#define KEYSPACE 16384      // id*8 + (snap-1), id < 2000 -> key < 16000

// ---- device scratch ----
__device__ uint32_t g_cnt[NELEM];      // hot: row idx (0..127). cold: 0x80000000|cx|cy<<11|s<<22
__device__ float4   g_hot[128*32];     // hot joint table (s<8, cx<4, cy<4), 64KB

// ============================================================
// Direct evaluation of one output row for (s, cx, cy).
// Warp-collective; lane holds float4 covering d' = 4*lane .. 4*lane+3.
// ============================================================
template <int UNROLL>
__device__ __forceinline__ float4 elem_eval(int s, int cx, int cy, int lane,
                              const float* __restrict__ aw1,
                              const float* __restrict__ ab1,
                              const float* __restrict__ aw2,
                              const float* __restrict__ ab2,
                              const float* __restrict__ ew1,
                              const float* __restrict__ eb1,
                              const float* __restrict__ ew2,
                              const float* __restrict__ eb2) {
    float fx = (float)cx, fy = (float)cy;
    float a0 = 0.f, a1 = 0.f;
#pragma unroll
    for (int m = 0; m < 4; ++m) {
        int d = lane + 32*m;
        float w = __ldg(&aw1[s*DD + d]);
        float b = __ldg(&ab1[d]);
        float h = fmaxf(fmaf(fx, w, b), 0.f) + fmaxf(fmaf(fy, w, b), 0.f);
        a0 = fmaf(h, __ldg(&aw2[2*d + 0]), a0);
        a1 = fmaf(h, __ldg(&aw2[2*d + 1]), a1);
    }
#pragma unroll
    for (int off = 16; off; off >>= 1) {
        a0 += __shfl_xor_sync(0xffffffffu, a0, off);
        a1 += __shfl_xor_sync(0xffffffffu, a1, off);
    }
    float y0 = fmaf(0.5f, a0, __ldg(&ab2[0]));
    float y1 = fmaf(0.5f, a1, __ldg(&ab2[1]));

    float4 e2 = __ldg(&((const float4*)eb2)[lane]);
    float4 acc;
    acc.x = 2.f*e2.x; acc.y = 2.f*e2.y; acc.z = 2.f*e2.z; acc.w = 2.f*e2.w;
    const float4* W2 = (const float4*)ew2;
#pragma unroll UNROLL
    for (int d = 0; d < DD; ++d) {
        float w = __ldg(&ew1[d]);
        float b = __ldg(&eb1[d]);
        float h = fmaxf(fmaf(y0, w, b), 0.f) + fmaxf(fmaf(y1, w, b), 0.f);
        float4 w2 = __ldg(&W2[d*32 + lane]);
        acc.x = fmaf(h, w2.x, acc.x);
        acc.y = fmaf(h, w2.y, acc.y);
        acc.z = fmaf(h, w2.z, acc.z);
        acc.w = fmaf(h, w2.w, acc.w);
    }
    return acc;
}

// Rare-path wrapper: noinline keeps registers out of the hot gather kernel.
__device__ __noinline__ float4 elem_direct(int s, int cx, int cy, int lane,
                              const float* __restrict__ aw1,
                              const float* __restrict__ ab1,
                              const float* __restrict__ aw2,
                              const float* __restrict__ ab2,
                              const float* __restrict__ ew1,
                              const float* __restrict__ eb1,
                              const float* __restrict__ ew2,
                              const float* __restrict__ eb2) {
    return elem_eval<4>(s, cx, cy, lane, aw1, ab1, aw2, ab2, ew1, eb1, ew2, eb2);
}

// ============================================================
// Fused kernel. Block roles by blockIdx.x:
//   [0,64)   : per-batch histogram count (64KB smem); emits decoded g_cnt
//   [64,128) : hot joint table, 2 rows per block (spread over 64 SMs)
// ============================================================
__global__ __launch_bounds__(1024, 1)
void k_fused(const int* __restrict__ sid, const int* __restrict__ did,
             const int* __restrict__ ssn, const int* __restrict__ dsn,
             const float* __restrict__ aw1, const float* __restrict__ ab1,
             const float* __restrict__ aw2, const float* __restrict__ ab2,
             const float* __restrict__ ew1, const float* __restrict__ eb1,
             const float* __restrict__ ew2, const float* __restrict__ eb2) {
    extern __shared__ uint32_t smraw[];
    int bid = blockIdx.x;
    int tid = threadIdx.x;

    if (bid < 64) {
        // ---------------- count section ----------------
        uint32_t* tabS = smraw;                // KEYSPACE/2 words
        uint32_t* tabD = smraw + KEYSPACE/2;
        int b = bid;
        uint4* z = (uint4*)smraw;
#pragma unroll
        for (int i = 0; i < 4; ++i) z[tid + i*1024] = make_uint4(0,0,0,0);
        __syncthreads();

        int i = b*LL + tid;
        unsigned k1 = (unsigned)(sid[i]*8 + (ssn[i]-1));
        unsigned k2 = (unsigned)(did[i]*8 + (dsn[i]-1));
        k1 = min(k1, (unsigned)(KEYSPACE-1));
        k2 = min(k2, (unsigned)(KEYSPACE-1));
        atomicAdd(&tabS[k1>>1], 1u << ((k1&1)*16));
        atomicAdd(&tabD[k2>>1], 1u << ((k2&1)*16));
        __syncthreads();

        uint32_t cxS = (tabS[k1>>1] >> ((k1&1)*16)) & 0xFFFFu;
        uint32_t cyS = (tabD[k1>>1] >> ((k1&1)*16)) & 0xFFFFu;
        uint32_t cxD = (tabD[k2>>1] >> ((k2&1)*16)) & 0xFFFFu;
        uint32_t cyD = (tabS[k2>>1] >> ((k2&1)*16)) & 0xFFFFu;
        if (k1 < 8) { cxS = 0; cyS = 0; }     // id == 0 -> invalid
        if (k2 < 8) { cxD = 0; cyD = 0; }
        unsigned s1 = k1 & 7u, s2 = k2 & 7u;
        uint32_t v1 = ((cxS | cyS) < 4u)
                    ? ((s1 << 4) | (cxS << 2) | cyS)
                    : (0x80000000u | cxS | (cyS << 11) | (s1 << 22));
        uint32_t v2 = ((cxD | cyD) < 4u)
                    ? ((s2 << 4) | (cxD << 2) | cyD)
                    : (0x80000000u | cxD | (cyD << 11) | (s2 << 22));
        g_cnt[     b*LL + tid] = v1;
        g_cnt[BL + b*LL + tid] = v2;

    } else {
        // ---------------- hot-table section: 2 rows per block ----------------
        int wid  = tid >> 5;
        int lane = tid & 31;
        if (wid < 2) {
            int ce = (bid - 64)*2 + wid;      // 0..127
            int s  = ce >> 4;
            int cx = (ce >> 2) & 3;
            int cy = ce & 3;
            g_hot[ce*32 + lane] = elem_eval<16>(s, cx, cy, lane,
                                                aw1, ab1, aw2, ab2,
                                                ew1, eb1, ew2, eb2);
        }
    }
}

// ============================================================
// Main kernel: FOUR elements per warp. One uint4 broadcast load of
// decoded pk words -> 4 independent L1 gather->STG.128 chains.
// Cold elements (MSB set): warp-collective direct MLP.
// ============================================================
__global__ __launch_bounds__(256, 8)
void k_main(const float* __restrict__ aw1, const float* __restrict__ ab1,
            const float* __restrict__ aw2, const float* __restrict__ ab2,
            const float* __restrict__ ew1, const float* __restrict__ eb1,
            const float* __restrict__ ew2, const float* __restrict__ eb2,
            float4* __restrict__ out) {
    int lane = threadIdx.x & 31;
    int w = blockIdx.x*8 + (threadIdx.x >> 5);   // warp id
    int base = w << 2;                           // 4 elements per warp

    uint4 pks = *(const uint4*)&g_cnt[base];     // broadcast uint4 load
    uint32_t pk[4] = {pks.x, pks.y, pks.z, pks.w};
    float4 r[4];
#pragma unroll
    for (int i = 0; i < 4; ++i) {
        if (!(pk[i] & 0x80000000u)) {            // hot: pk IS the row index
            r[i] = g_hot[(pk[i] << 5) + lane];
        } else {
            int cx = pk[i] & 0x7FF;
            int cy = (pk[i] >> 11) & 0x7FF;
            int s  = (pk[i] >> 22) & 0xFF;
            r[i] = elem_direct(s, cx, cy, lane,
                               aw1, ab1, aw2, ab2, ew1, eb1, ew2, eb2);
        }
    }
#pragma unroll
    for (int i = 0; i < 4; ++i)
        __stcs(&out[(size_t)(base + i)*32 + lane], r[i]);
}

// ============================================================
extern "C" void kernel_launch(void* const* d_in, const int* in_sizes, int n_in,
                              void* d_out, int out_size) {
    const int*   sid = (const int*)d_in[0];
    const int*   did = (const int*)d_in[1];
    const int*   ssn = (const int*)d_in[2];
    const int*   dsn = (const int*)d_in[3];
    const float* aw1 = (const float*)d_in[5];
    const float* ab1 = (const float*)d_in[6];
    const float* aw2 = (const float*)d_in[7];
    const float* ab2 = (const float*)d_in[8];
    const float* ew1 = (const float*)d_in[9];
    const float* eb1 = (const float*)d_in[10];
    const float* ew2 = (const float*)d_in[11];
    const float* eb2 = (const float*)d_in[12];
    float4* out = (float4*)d_out;

    size_t fusedSmem = (size_t)KEYSPACE * sizeof(uint32_t);   // 64 KB
    cudaFuncSetAttribute(k_fused, cudaFuncAttributeMaxDynamicSharedMemorySize, (int)fusedSmem);

    k_fused<<<128, 1024, fusedSmem>>>(sid, did, ssn, dsn,
                                      aw1, ab1, aw2, ab2, ew1, eb1, ew2, eb2);
    k_main<<<NELEM/32, 256>>>(aw1, ab1, aw2, ab2, ew1, eb1, ew2, eb2, out);
}